// round 11
// baseline (speedup 1.0000x reference)
#include <cuda_runtime.h>
#include <cstdint>

// Problem constants (from reference)
#define GB_T 1000000
#define GB_C 16
#define GB_G 500000
#define GB_K 9
#define GB_GK (GB_G * GB_K)              // 4,500,000 (g,k) rows
#define GB_PER_B (GB_GK * 4)             // 18,000,000 float4s per batch
#define GB_PER_STAGE (GB_GK * 2)         // 9,000,000 float4s per (batch, phase)
#define GB_UNROLL 4
#define GB_STRIDE (GB_PER_STAGE / GB_UNROLL)  // 2,250,000 (exact)

// Phase-split gather: phase p handles the 32-byte half [32p, 32p+32) of every
// 64-byte texel row. Sector-granular (32B) L2 fills mean each phase's texture
// working set is 32MB/batch instead of 64MB -> texel reuses hit in L2 before
// the 576MB store stream churns the line out.
__global__ __launch_bounds__(256)
void gather_groups_kernel(const float4* __restrict__ tex4,   // [B, T*4] float4
                          const int*    __restrict__ gidx,   // [G*K]
                          float4*       __restrict__ out4)   // [B, G*K*4]
{
    const int tid = blockIdx.x * blockDim.x + threadIdx.x;
    if (tid >= GB_STRIDE) return;
    const int phase = blockIdx.y;    // 0/1: which 32B half of each row
    const int b     = blockIdx.z;    // batch (slowest raster dim -> batch-serial)

    const int64_t tex_base = (int64_t)b * (GB_T * 4);
    const int64_t out_base = (int64_t)b * GB_PER_B;
    const int     c4_base  = phase * 2;

    // Front-batch 4 independent index loads (2 consecutive threads share one idx)
    int idx[GB_UNROLL];
#pragma unroll
    for (int u = 0; u < GB_UNROLL; u++) {
        const int e = tid + u * GB_STRIDE;           // float4-chunk id within stage
        idx[u] = __ldg(&gidx[e >> 1]);
    }

    // Front-batch 4 independent 16B gathers (MLP=4) from this phase's half-rows
    float4 v[GB_UNROLL];
#pragma unroll
    for (int u = 0; u < GB_UNROLL; u++) {
        const int e  = tid + u * GB_STRIDE;
        const int c4 = c4_base + (e & 1);
        v[u] = __ldg(&tex4[tex_base + (int64_t)idx[u] * 4 + c4]);
    }

    // Evict-first streaming stores (proven in R2). Thread pairs write 32B
    // contiguous segments at 64B stride -> all 32B sectors fully covered.
#pragma unroll
    for (int u = 0; u < GB_UNROLL; u++) {
        const int e  = tid + u * GB_STRIDE;
        const int gk = e >> 1;
        const int c4 = c4_base + (e & 1);
        __stcs(&out4[out_base + (int64_t)gk * 4 + c4], v[u]);
    }
}

extern "C" void kernel_launch(void* const* d_in, const int* in_sizes, int n_in,
                              void* d_out, int out_size) {
    // metadata order: mesh_ids (int32 [B]) — unused by reference math,
    //                 textures (float32 [B,T,C]), group_idx (int32 [G,K])
    const float4* tex4 = (const float4*)d_in[1];
    const int*    gidx = (const int*)d_in[2];
    float4*       out4 = (float4*)d_out;

    const int threads = 256;
    const int blocks = (GB_STRIDE + threads - 1) / threads;  // 8790
    // Raster order x -> y(phase) -> z(batch): each (batch,phase) stage runs
    // ~serially, keeping the live texture sector set at ~32MB.
    dim3 grid(blocks, 2, 2);

    gather_groups_kernel<<<grid, threads>>>(tex4, gidx, out4);
}